// round 1
// baseline (speedup 1.0000x reference)
#include <cuda_runtime.h>
#include <math.h>

#define T_TOK 4096
#define H_DIM 2048
#define I_DIM 768
#define E_NUM 8

#define TM 128
#define TN 128
#define TKK 16

// ---- scratch (device globals; no allocation allowed) ----
__device__ int   g_cnt[E_NUM];
__device__ int   g_tok[E_NUM * T_TOK];
__device__ float g_wt [E_NUM * T_TOK];
__device__ float g_gup[(size_t)E_NUM * T_TOK * (2 * I_DIM)]; // gate|up, per (e,slot)
__device__ float g_act[(size_t)E_NUM * T_TOK * I_DIM];       // silu(g)*u

// ---------------------------------------------------------------------------
__global__ void k_init() {
    if (threadIdx.x < E_NUM) g_cnt[threadIdx.x] = 0;
}

// ---------------------------------------------------------------------------
// Router: 1 warp per token. logits = x @ w_router; top-2; weights from
// softmax over just the two top logits (full-softmax denominator cancels).
__global__ void k_router(const float* __restrict__ x,
                         const float* __restrict__ wr,
                         float* __restrict__ out_logits,
                         int write_logits) {
    int warp = threadIdx.x >> 5;
    int lane = threadIdx.x & 31;
    int t = blockIdx.x * 8 + warp;
    if (t >= T_TOK) return;

    float acc[E_NUM];
#pragma unroll
    for (int e = 0; e < E_NUM; e++) acc[e] = 0.f;

    const float* xp = x + (size_t)t * H_DIM;
    for (int h = lane; h < H_DIM; h += 32) {
        float xv = xp[h];
        const float* w = wr + (size_t)h * E_NUM;
#pragma unroll
        for (int e = 0; e < E_NUM; e++) acc[e] += xv * w[e];
    }
#pragma unroll
    for (int e = 0; e < E_NUM; e++) {
#pragma unroll
        for (int o = 16; o > 0; o >>= 1)
            acc[e] += __shfl_xor_sync(0xffffffffu, acc[e], o);
    }

    if (lane == 0) {
        if (write_logits) {
#pragma unroll
            for (int e = 0; e < E_NUM; e++)
                out_logits[(size_t)t * E_NUM + e] = acc[e];
        }
        // top-2 (ties -> lowest index, matching jax.lax.top_k)
        int i1 = 0;
#pragma unroll
        for (int e = 1; e < E_NUM; e++) if (acc[e] > acc[i1]) i1 = e;
        int i2 = (i1 == 0) ? 1 : 0;
#pragma unroll
        for (int e = 0; e < E_NUM; e++)
            if (e != i1 && acc[e] > acc[i2]) i2 = e;

        float p2 = expf(acc[i2] - acc[i1]);
        float w1 = 1.f / (1.f + p2);
        float w2 = p2 * w1;

        int p;
        p = atomicAdd(&g_cnt[i1], 1);
        g_tok[i1 * T_TOK + p] = t; g_wt[i1 * T_TOK + p] = w1;
        p = atomicAdd(&g_cnt[i2], 1);
        g_tok[i2 * T_TOK + p] = t; g_wt[i2 * T_TOK + p] = w2;
    }
}

// ---------------------------------------------------------------------------
// Grouped GEMM 1: per expert e,  [Ne, H] x [H, 2I]  -> g_gup
// N-tiles 0..5 read wi0 (gate), 6..11 read wi1 (up).
__global__ __launch_bounds__(256, 2)
void k_gateup(const float* __restrict__ x,
              const float* __restrict__ wi0,
              const float* __restrict__ wi1) {
    int e  = blockIdx.z;
    int ne = g_cnt[e];
    int m0 = blockIdx.x * TM;
    if (m0 >= ne) return;
    int by = blockIdx.y;  // 0..11

    const float* wbase = (by < 6)
        ? (wi0 + (size_t)e * H_DIM * I_DIM + (size_t)by * TN)
        : (wi1 + (size_t)e * H_DIM * I_DIM + (size_t)(by - 6) * TN);

    __shared__ __align__(16) float As[TKK][TM + 4];
    __shared__ __align__(16) float Bs[TKK][TN + 4];

    int tid = threadIdx.x;
    int ar = tid >> 1;            // 0..127
    int ak = (tid & 1) * 8;       // 0 or 8
    bool avalid = (m0 + ar < ne);
    const float* aptr = x;        // dummy
    if (avalid)
        aptr = x + (size_t)g_tok[e * T_TOK + m0 + ar] * H_DIM + ak;

    int bk = tid >> 4;            // 0..15
    int bn = (tid & 15) * 8;      // 0..120
    const float* bptr = wbase + (size_t)bk * I_DIM + bn;

    int tx = tid & 15, ty = tid >> 4;
    float c[8][8];
#pragma unroll
    for (int i = 0; i < 8; i++)
#pragma unroll
        for (int j = 0; j < 8; j++) c[i][j] = 0.f;

    for (int k0 = 0; k0 < H_DIM; k0 += TKK) {
        float4 a0 = make_float4(0, 0, 0, 0), a1 = make_float4(0, 0, 0, 0);
        if (avalid) {
            a0 = *(const float4*)(aptr);
            a1 = *(const float4*)(aptr + 4);
        }
        aptr += TKK;
        float4 b0 = *(const float4*)(bptr);
        float4 b1 = *(const float4*)(bptr + 4);
        bptr += (size_t)TKK * I_DIM;

        __syncthreads();
        As[ak + 0][ar] = a0.x; As[ak + 1][ar] = a0.y;
        As[ak + 2][ar] = a0.z; As[ak + 3][ar] = a0.w;
        As[ak + 4][ar] = a1.x; As[ak + 5][ar] = a1.y;
        As[ak + 6][ar] = a1.z; As[ak + 7][ar] = a1.w;
        *(float4*)&Bs[bk][bn]     = b0;
        *(float4*)&Bs[bk][bn + 4] = b1;
        __syncthreads();

#pragma unroll
        for (int k = 0; k < TKK; k++) {
            float4 av0 = *(const float4*)&As[k][ty * 8];
            float4 av1 = *(const float4*)&As[k][ty * 8 + 4];
            float4 bv0 = *(const float4*)&Bs[k][tx * 8];
            float4 bv1 = *(const float4*)&Bs[k][tx * 8 + 4];
            float a[8] = {av0.x, av0.y, av0.z, av0.w, av1.x, av1.y, av1.z, av1.w};
            float b[8] = {bv0.x, bv0.y, bv0.z, bv0.w, bv1.x, bv1.y, bv1.z, bv1.w};
#pragma unroll
            for (int i = 0; i < 8; i++)
#pragma unroll
                for (int j = 0; j < 8; j++) c[i][j] += a[i] * b[j];
        }
    }

    size_t base = ((size_t)e * T_TOK + m0) * (size_t)(2 * I_DIM) + (size_t)by * TN;
#pragma unroll
    for (int i = 0; i < 8; i++) {
        int m = ty * 8 + i;
        if (m0 + m < ne) {
            float* dst = g_gup + base + (size_t)m * (2 * I_DIM) + tx * 8;
            *(float4*)dst       = make_float4(c[i][0], c[i][1], c[i][2], c[i][3]);
            *(float4*)(dst + 4) = make_float4(c[i][4], c[i][5], c[i][6], c[i][7]);
        }
    }
}

// ---------------------------------------------------------------------------
// silu(gate) * up -> g_act
__global__ void k_silu() {
    const int IV = I_DIM / 4;                       // 192
    size_t idx = (size_t)blockIdx.x * blockDim.x + threadIdx.x;
    int slotg = (int)(idx / IV);                    // 0..E*T-1
    int iv    = (int)(idx % IV);
    int e = slotg >> 12;                            // /4096
    int s = slotg & 4095;
    if (s >= g_cnt[e]) return;

    const float4 g4 = *(const float4*)(g_gup + (size_t)slotg * (2 * I_DIM) + iv * 4);
    const float4 u4 = *(const float4*)(g_gup + (size_t)slotg * (2 * I_DIM) + I_DIM + iv * 4);
    float4 r;
    r.x = (g4.x / (1.f + expf(-g4.x))) * u4.x;
    r.y = (g4.y / (1.f + expf(-g4.y))) * u4.y;
    r.z = (g4.z / (1.f + expf(-g4.z))) * u4.z;
    r.w = (g4.w / (1.f + expf(-g4.w))) * u4.w;
    *(float4*)(g_act + (size_t)slotg * I_DIM + iv * 4) = r;
}

// ---------------------------------------------------------------------------
// Grouped GEMM 2: per expert e, [Ne, I] x [I, H], weighted scatter-add to out.
__global__ __launch_bounds__(256, 2)
void k_down(const float* __restrict__ wo, float* __restrict__ out) {
    int e  = blockIdx.z;
    int ne = g_cnt[e];
    int m0 = blockIdx.x * TM;
    if (m0 >= ne) return;
    int n0 = blockIdx.y * TN;

    const float* wbase = wo + (size_t)e * I_DIM * H_DIM + n0;

    __shared__ __align__(16) float As[TKK][TM + 4];
    __shared__ __align__(16) float Bs[TKK][TN + 4];

    int tid = threadIdx.x;
    int ar = tid >> 1;
    int ak = (tid & 1) * 8;
    bool avalid = (m0 + ar < ne);
    const float* aptr = g_act;
    if (avalid)
        aptr = g_act + ((size_t)e * T_TOK + m0 + ar) * I_DIM + ak;

    int bk = tid >> 4;
    int bn = (tid & 15) * 8;
    const float* bptr = wbase + (size_t)bk * H_DIM + bn;

    int tx = tid & 15, ty = tid >> 4;
    float c[8][8];
#pragma unroll
    for (int i = 0; i < 8; i++)
#pragma unroll
        for (int j = 0; j < 8; j++) c[i][j] = 0.f;

    for (int k0 = 0; k0 < I_DIM; k0 += TKK) {
        float4 a0 = make_float4(0, 0, 0, 0), a1 = make_float4(0, 0, 0, 0);
        if (avalid) {
            a0 = *(const float4*)(aptr);
            a1 = *(const float4*)(aptr + 4);
        }
        aptr += TKK;
        float4 b0 = *(const float4*)(bptr);
        float4 b1 = *(const float4*)(bptr + 4);
        bptr += (size_t)TKK * H_DIM;

        __syncthreads();
        As[ak + 0][ar] = a0.x; As[ak + 1][ar] = a0.y;
        As[ak + 2][ar] = a0.z; As[ak + 3][ar] = a0.w;
        As[ak + 4][ar] = a1.x; As[ak + 5][ar] = a1.y;
        As[ak + 6][ar] = a1.z; As[ak + 7][ar] = a1.w;
        *(float4*)&Bs[bk][bn]     = b0;
        *(float4*)&Bs[bk][bn + 4] = b1;
        __syncthreads();

#pragma unroll
        for (int k = 0; k < TKK; k++) {
            float4 av0 = *(const float4*)&As[k][ty * 8];
            float4 av1 = *(const float4*)&As[k][ty * 8 + 4];
            float4 bv0 = *(const float4*)&Bs[k][tx * 8];
            float4 bv1 = *(const float4*)&Bs[k][tx * 8 + 4];
            float a[8] = {av0.x, av0.y, av0.z, av0.w, av1.x, av1.y, av1.z, av1.w};
            float b[8] = {bv0.x, bv0.y, bv0.z, bv0.w, bv1.x, bv1.y, bv1.z, bv1.w};
#pragma unroll
            for (int i = 0; i < 8; i++)
#pragma unroll
                for (int j = 0; j < 8; j++) c[i][j] += a[i] * b[j];
        }
    }

#pragma unroll
    for (int i = 0; i < 8; i++) {
        int m = ty * 8 + i;
        if (m0 + m < ne) {
            int   t = g_tok[e * T_TOK + m0 + m];
            float w = g_wt [e * T_TOK + m0 + m];
            float* op = out + (size_t)t * H_DIM + n0 + tx * 8;
#pragma unroll
            for (int j = 0; j < 8; j++) atomicAdd(op + j, w * c[i][j]);
        }
    }
}

// ---------------------------------------------------------------------------
extern "C" void kernel_launch(void* const* d_in, const int* in_sizes, int n_in,
                              void* d_out, int out_size) {
    const float* x   = (const float*)d_in[0];  // hidden_states [B,S,H]
    const float* wr  = (const float*)d_in[1];  // w_router [H,E]
    const float* wi0 = (const float*)d_in[2];  // [E,H,I]
    const float* wi1 = (const float*)d_in[3];  // [E,H,I]
    const float* wo  = (const float*)d_in[4];  // [E,I,H]
    float* out = (float*)d_out;

    int write_logits =
        (out_size >= T_TOK * H_DIM + T_TOK * E_NUM) ? 1 : 0;

    cudaMemsetAsync(out, 0, (size_t)T_TOK * H_DIM * sizeof(float));
    k_init<<<1, 32>>>();
    k_router<<<T_TOK / 8, 256>>>(x, wr, out + (size_t)T_TOK * H_DIM, write_logits);

    dim3 g1(T_TOK / TM, (2 * I_DIM) / TN, E_NUM);
    k_gateup<<<g1, 256>>>(x, wi0, wi1);

    int silu_blocks = (E_NUM * T_TOK * (I_DIM / 4)) / 256;
    k_silu<<<silu_blocks, 256>>>();

    dim3 g2(T_TOK / TM, H_DIM / TN, E_NUM);
    k_down<<<g2, 256>>>(wo, out);
}

// round 3
// speedup vs baseline: 2.0821x; 2.0821x over previous
#include <cuda_runtime.h>
#include <cuda_fp16.h>
#include <cstdint>
#include <math.h>

#define T_TOK 4096
#define H_DIM 2048
#define I_DIM 768
#define E_NUM 8

// ---- scratch (device globals; no allocation allowed) ----
__device__ int    g_cnt[E_NUM];
__device__ int    g_tok[E_NUM * T_TOK];
__device__ float  g_wt [E_NUM * T_TOK];
__device__ float  g_gup[(size_t)E_NUM * T_TOK * (2 * I_DIM)];   // gate|up fp32
__device__ __half g_acth[(size_t)E_NUM * T_TOK * I_DIM];
__device__ __half g_actl[(size_t)E_NUM * T_TOK * I_DIM];
__device__ __half g_xh [(size_t)T_TOK * H_DIM];
__device__ __half g_xl [(size_t)T_TOK * H_DIM];
__device__ __half g_w0h[(size_t)E_NUM * H_DIM * I_DIM];
__device__ __half g_w0l[(size_t)E_NUM * H_DIM * I_DIM];
__device__ __half g_w1h[(size_t)E_NUM * H_DIM * I_DIM];
__device__ __half g_w1l[(size_t)E_NUM * H_DIM * I_DIM];
__device__ __half g_woh[(size_t)E_NUM * I_DIM * H_DIM];
__device__ __half g_wol[(size_t)E_NUM * I_DIM * H_DIM];

// ============================ helpers ====================================
__device__ __forceinline__ uint32_t smem_u32(const void* p) {
    uint32_t a;
    asm("{ .reg .u64 t; cvta.to.shared.u64 t, %1; cvt.u32.u64 %0, t; }" : "=r"(a) : "l"(p));
    return a;
}
__device__ __forceinline__ void ldm_x4(uint32_t* r, uint32_t a) {
    asm volatile("ldmatrix.sync.aligned.m8n8.x4.shared.b16 {%0,%1,%2,%3}, [%4];"
                 : "=r"(r[0]), "=r"(r[1]), "=r"(r[2]), "=r"(r[3]) : "r"(a));
}
__device__ __forceinline__ void ldm_x4_t(uint32_t* r, uint32_t a) {
    asm volatile("ldmatrix.sync.aligned.m8n8.x4.trans.shared.b16 {%0,%1,%2,%3}, [%4];"
                 : "=r"(r[0]), "=r"(r[1]), "=r"(r[2]), "=r"(r[3]) : "r"(a));
}
__device__ __forceinline__ void mma16816(float* c, const uint32_t* a, uint32_t b0, uint32_t b1) {
    asm volatile("mma.sync.aligned.m16n8k16.row.col.f32.f16.f16.f32 "
                 "{%0,%1,%2,%3}, {%4,%5,%6,%7}, {%8,%9}, {%0,%1,%2,%3};"
                 : "+f"(c[0]), "+f"(c[1]), "+f"(c[2]), "+f"(c[3])
                 : "r"(a[0]), "r"(a[1]), "r"(a[2]), "r"(a[3]), "r"(b0), "r"(b1));
}

// ---------------------------------------------------------------------------
__global__ void k_init() { if (threadIdx.x < E_NUM) g_cnt[threadIdx.x] = 0; }

// fp32 -> hi/lo fp16 planes (float4 granularity)
__global__ void k_cvt(const float* __restrict__ s, __half* __restrict__ hi,
                      __half* __restrict__ lo, int n4) {
    int i = blockIdx.x * blockDim.x + threadIdx.x;
    if (i >= n4) return;
    float4 v = ((const float4*)s)[i];
    __half h0 = __float2half_rn(v.x), h1 = __float2half_rn(v.y);
    __half h2 = __float2half_rn(v.z), h3 = __float2half_rn(v.w);
    __half l0 = __float2half_rn(v.x - __half2float(h0));
    __half l1 = __float2half_rn(v.y - __half2float(h1));
    __half l2 = __float2half_rn(v.z - __half2float(h2));
    __half l3 = __float2half_rn(v.w - __half2float(h3));
    ((__half2*)hi)[2 * i]     = __halves2half2(h0, h1);
    ((__half2*)hi)[2 * i + 1] = __halves2half2(h2, h3);
    ((__half2*)lo)[2 * i]     = __halves2half2(l0, l1);
    ((__half2*)lo)[2 * i + 1] = __halves2half2(l2, l3);
}

// ---------------------------------------------------------------------------
// Router: 1 warp/token, top-2 softmax over selected pair.
__global__ void k_router(const float* __restrict__ x, const float* __restrict__ wr,
                         float* __restrict__ out_logits, int write_logits) {
    int warp = threadIdx.x >> 5, lane = threadIdx.x & 31;
    int t = blockIdx.x * 8 + warp;
    if (t >= T_TOK) return;
    float acc[E_NUM];
#pragma unroll
    for (int e = 0; e < E_NUM; e++) acc[e] = 0.f;
    const float* xp = x + (size_t)t * H_DIM;
    for (int h = lane; h < H_DIM; h += 32) {
        float xv = xp[h];
        const float* w = wr + (size_t)h * E_NUM;
#pragma unroll
        for (int e = 0; e < E_NUM; e++) acc[e] += xv * w[e];
    }
#pragma unroll
    for (int e = 0; e < E_NUM; e++)
#pragma unroll
        for (int o = 16; o > 0; o >>= 1)
            acc[e] += __shfl_xor_sync(0xffffffffu, acc[e], o);
    if (lane == 0) {
        if (write_logits)
#pragma unroll
            for (int e = 0; e < E_NUM; e++)
                out_logits[(size_t)t * E_NUM + e] = acc[e];
        int i1 = 0;
#pragma unroll
        for (int e = 1; e < E_NUM; e++) if (acc[e] > acc[i1]) i1 = e;
        int i2 = (i1 == 0) ? 1 : 0;
#pragma unroll
        for (int e = 0; e < E_NUM; e++)
            if (e != i1 && acc[e] > acc[i2]) i2 = e;
        float p2 = expf(acc[i2] - acc[i1]);
        float w1 = 1.f / (1.f + p2), w2 = p2 * w1;
        int p;
        p = atomicAdd(&g_cnt[i1], 1);
        g_tok[i1 * T_TOK + p] = t; g_wt[i1 * T_TOK + p] = w1;
        p = atomicAdd(&g_cnt[i2], 1);
        g_tok[i2 * T_TOK + p] = t; g_wt[i2 * T_TOK + p] = w2;
    }
}

// ---------------------------------------------------------------------------
// GEMM core notes:
//  BM=128, BN=128, BK=16, 256 threads, warp grid 2(M)x4(N), warp tile 64x32.
//  smem/buffer: Ah 4K | Al 4K | Bh 4K | Bl 4K  (A:[128m][16k], B:[16k][128n])
//  A swizzle (32B rows):  off ^ (((row>>2)&1)<<4)
//  B swizzle (256B rows): off ^ ((k&7)<<4)
//  fp16x3: D += Ah*Bh + Ah*Bl + Al*Bh

__global__ __launch_bounds__(256)
void k_mlp1() {
    __shared__ __align__(16) char sm[2][16384];
    int e  = blockIdx.z;
    int ne = g_cnt[e];
    int m0 = blockIdx.x * 128;
    if (m0 >= ne) return;
    int by = blockIdx.y;  // 0..11: 0-5 gate(wi0), 6-11 up(wi1)

    const __half* bph = (by < 6 ? g_w0h : g_w1h) + (size_t)e * H_DIM * I_DIM + (by % 6) * 128;
    const __half* bpl = (by < 6 ? g_w0l : g_w1l) + (size_t)e * H_DIM * I_DIM + (by % 6) * 128;

    int tid = threadIdx.x, lane = tid & 31, wid = tid >> 5;
    int warpM = (wid >> 2) * 64, warpN = (wid & 3) * 32;
    uint32_t sbase = smem_u32(sm);

    // fill maps
    int ar = tid >> 1;
    uint32_t aswz = (uint32_t)(ar * 32) +
                    (((uint32_t)((tid & 1) * 16)) ^ ((((uint32_t)ar >> 2) & 1) << 4));
    bool av = (m0 + ar) < ne;
    size_t aoff = 0;
    if (av) aoff = (size_t)g_tok[e * T_TOK + m0 + ar] * H_DIM + (tid & 1) * 8;

    int bkk = tid & 15, bat = tid >> 4;
    uint32_t bswz = (uint32_t)(bkk * 256) + ((uint32_t)(bat ^ (bkk & 7)) << 4);
    size_t boff = (size_t)bkk * I_DIM + bat * 8;

    float c[4][4][4];
#pragma unroll
    for (int i = 0; i < 4; i++)
#pragma unroll
        for (int j = 0; j < 4; j++)
#pragma unroll
            for (int q = 0; q < 4; q++) c[i][j][q] = 0.f;

    uint4 pah, pal, pbh, pbl;
#define LDG1(K0) do {                                                        \
    if (av) { pah = *(const uint4*)(g_xh + aoff + (K0));                     \
              pal = *(const uint4*)(g_xl + aoff + (K0)); }                   \
    else { pah = make_uint4(0,0,0,0); pal = make_uint4(0,0,0,0); }           \
    pbh = *(const uint4*)(bph + boff + (size_t)(K0) * I_DIM);                \
    pbl = *(const uint4*)(bpl + boff + (size_t)(K0) * I_DIM);                \
} while (0)
#define STS1(BUF) do {                                                       \
    char* s_ = sm[BUF];                                                      \
    *(uint4*)(s_ + aswz)          = pah;                                     \
    *(uint4*)(s_ + 4096  + aswz)  = pal;                                     \
    *(uint4*)(s_ + 8192  + bswz)  = pbh;                                     \
    *(uint4*)(s_ + 12288 + bswz)  = pbl;                                     \
} while (0)

    LDG1(0); STS1(0); __syncthreads();

    int arow_l = warpM + (lane & 15);
    uint32_t acol_l = (uint32_t)((lane >> 4) * 16);
    int bk_l = (lane & 7) + ((lane >> 3) & 1) * 8;
    int bnat_l = (warpN >> 3) + ((lane >> 4) & 1);

    const int NC = H_DIM / 16;
    for (int cc = 0; cc < NC; cc++) {
        int cur = cc & 1;
        bool more = (cc + 1) < NC;
        if (more) LDG1((cc + 1) * 16);

        uint32_t sb0 = sbase + cur * 16384;
        uint32_t Af[4][4], Al_[4][4], Bf[2][4], Bl_[2][4];
#pragma unroll
        for (int i = 0; i < 4; i++) {
            int row = arow_l + i * 16;
            uint32_t ad = sb0 + row * 32 + (acol_l ^ ((((uint32_t)row >> 2) & 1) << 4));
            ldm_x4(Af[i], ad);
            ldm_x4(Al_[i], ad + 4096);
        }
#pragma unroll
        for (int jj = 0; jj < 2; jj++) {
            int nat = bnat_l + jj * 2;
            uint32_t bd = sb0 + 8192 + bk_l * 256 + ((uint32_t)(nat ^ (bk_l & 7)) << 4);
            ldm_x4_t(Bf[jj], bd);
            ldm_x4_t(Bl_[jj], bd + 4096);
        }
#pragma unroll
        for (int i = 0; i < 4; i++)
#pragma unroll
            for (int j = 0; j < 4; j++) {
                int jj = j >> 1, o = (j & 1) * 2;
                mma16816(c[i][j], Af[i],  Bf[jj][o],  Bf[jj][o + 1]);
                mma16816(c[i][j], Af[i],  Bl_[jj][o], Bl_[jj][o + 1]);
                mma16816(c[i][j], Al_[i], Bf[jj][o],  Bf[jj][o + 1]);
            }
        if (more) { __syncthreads(); STS1(cur ^ 1); __syncthreads(); }
    }

    int gr = lane >> 2, gc = (lane & 3) * 2;
#pragma unroll
    for (int i = 0; i < 4; i++) {
        int r0 = warpM + i * 16 + gr;
#pragma unroll
        for (int j = 0; j < 4; j++) {
            int col = by * 128 + warpN + j * 8 + gc;
            if (m0 + r0 < ne)
                *(float2*)&g_gup[((size_t)e * T_TOK + m0 + r0) * (2 * I_DIM) + col] =
                    make_float2(c[i][j][0], c[i][j][1]);
            if (m0 + r0 + 8 < ne)
                *(float2*)&g_gup[((size_t)e * T_TOK + m0 + r0 + 8) * (2 * I_DIM) + col] =
                    make_float2(c[i][j][2], c[i][j][3]);
        }
    }
#undef LDG1
#undef STS1
}

// ---------------------------------------------------------------------------
// silu(gate)*up -> hi/lo fp16 planes
__global__ void k_silu() {
    const int IV = I_DIM / 4;
    size_t idx = (size_t)blockIdx.x * blockDim.x + threadIdx.x;
    int slotg = (int)(idx / IV);
    int iv = (int)(idx % IV);
    int e = slotg >> 12, s = slotg & 4095;
    if (s >= g_cnt[e]) return;
    const float4 g4 = *(const float4*)(g_gup + (size_t)slotg * (2 * I_DIM) + iv * 4);
    const float4 u4 = *(const float4*)(g_gup + (size_t)slotg * (2 * I_DIM) + I_DIM + iv * 4);
    float r0 = (g4.x / (1.f + expf(-g4.x))) * u4.x;
    float r1 = (g4.y / (1.f + expf(-g4.y))) * u4.y;
    float r2 = (g4.z / (1.f + expf(-g4.z))) * u4.z;
    float r3 = (g4.w / (1.f + expf(-g4.w))) * u4.w;
    __half h0 = __float2half_rn(r0), h1 = __float2half_rn(r1);
    __half h2 = __float2half_rn(r2), h3 = __float2half_rn(r3);
    __half l0 = __float2half_rn(r0 - __half2float(h0));
    __half l1 = __float2half_rn(r1 - __half2float(h1));
    __half l2 = __float2half_rn(r2 - __half2float(h2));
    __half l3 = __float2half_rn(r3 - __half2float(h3));
    __half2* ph = (__half2*)(g_acth + (size_t)slotg * I_DIM + iv * 4);
    ph[0] = __halves2half2(h0, h1); ph[1] = __halves2half2(h2, h3);
    __half2* pl = (__half2*)(g_actl + (size_t)slotg * I_DIM + iv * 4);
    pl[0] = __halves2half2(l0, l1); pl[1] = __halves2half2(l2, l3);
}

// ---------------------------------------------------------------------------
__global__ __launch_bounds__(256)
void k_mlp2(float* __restrict__ out) {
    __shared__ __align__(16) char sm[2][16384];
    int e  = blockIdx.z;
    int ne = g_cnt[e];
    int m0 = blockIdx.x * 128;
    if (m0 >= ne) return;
    int n0 = blockIdx.y * 128;

    const __half* bph = g_woh + (size_t)e * I_DIM * H_DIM + n0;
    const __half* bpl = g_wol + (size_t)e * I_DIM * H_DIM + n0;

    int tid = threadIdx.x, lane = tid & 31, wid = tid >> 5;
    int warpM = (wid >> 2) * 64, warpN = (wid & 3) * 32;
    uint32_t sbase = smem_u32(sm);

    int ar = tid >> 1;
    uint32_t aswz = (uint32_t)(ar * 32) +
                    (((uint32_t)((tid & 1) * 16)) ^ ((((uint32_t)ar >> 2) & 1) << 4));
    bool av = (m0 + ar) < ne;
    size_t aoff = ((size_t)e * T_TOK + m0 + ar) * I_DIM + (tid & 1) * 8;

    int bkk = tid & 15, bat = tid >> 4;
    uint32_t bswz = (uint32_t)(bkk * 256) + ((uint32_t)(bat ^ (bkk & 7)) << 4);
    size_t boff = (size_t)bkk * H_DIM + bat * 8;

    float c[4][4][4];
#pragma unroll
    for (int i = 0; i < 4; i++)
#pragma unroll
        for (int j = 0; j < 4; j++)
#pragma unroll
            for (int q = 0; q < 4; q++) c[i][j][q] = 0.f;

    uint4 pah, pal, pbh, pbl;
#define LDG2(K0) do {                                                        \
    if (av) { pah = *(const uint4*)(g_acth + aoff + (K0));                   \
              pal = *(const uint4*)(g_actl + aoff + (K0)); }                 \
    else { pah = make_uint4(0,0,0,0); pal = make_uint4(0,0,0,0); }           \
    pbh = *(const uint4*)(bph + boff + (size_t)(K0) * H_DIM);                \
    pbl = *(const uint4*)(bpl + boff + (size_t)(K0) * H_DIM);                \
} while (0)
#define STS2(BUF) do {                                                       \
    char* s_ = sm[BUF];                                                      \
    *(uint4*)(s_ + aswz)          = pah;                                     \
    *(uint4*)(s_ + 4096  + aswz)  = pal;                                     \
    *(uint4*)(s_ + 8192  + bswz)  = pbh;                                     \
    *(uint4*)(s_ + 12288 + bswz)  = pbl;                                     \
} while (0)

    LDG2(0); STS2(0); __syncthreads();

    int arow_l = warpM + (lane & 15);
    uint32_t acol_l = (uint32_t)((lane >> 4) * 16);
    int bk_l = (lane & 7) + ((lane >> 3) & 1) * 8;
    int bnat_l = (warpN >> 3) + ((lane >> 4) & 1);

    const int NC = I_DIM / 16;
    for (int cc = 0; cc < NC; cc++) {
        int cur = cc & 1;
        bool more = (cc + 1) < NC;
        if (more) LDG2((cc + 1) * 16);

        uint32_t sb0 = sbase + cur * 16384;
        uint32_t Af[4][4], Al_[4][4], Bf[2][4], Bl_[2][4];
#pragma unroll
        for (int i = 0; i < 4; i++) {
            int row = arow_l + i * 16;
            uint32_t ad = sb0 + row * 32 + (acol_l ^ ((((uint32_t)row >> 2) & 1) << 4));
            ldm_x4(Af[i], ad);
            ldm_x4(Al_[i], ad + 4096);
        }
#pragma unroll
        for (int jj = 0; jj < 2; jj++) {
            int nat = bnat_l + jj * 2;
            uint32_t bd = sb0 + 8192 + bk_l * 256 + ((uint32_t)(nat ^ (bk_l & 7)) << 4);
            ldm_x4_t(Bf[jj], bd);
            ldm_x4_t(Bl_[jj], bd + 4096);
        }
#pragma unroll
        for (int i = 0; i < 4; i++)
#pragma unroll
            for (int j = 0; j < 4; j++) {
                int jj = j >> 1, o = (j & 1) * 2;
                mma16816(c[i][j], Af[i],  Bf[jj][o],  Bf[jj][o + 1]);
                mma16816(c[i][j], Af[i],  Bl_[jj][o], Bl_[jj][o + 1]);
                mma16816(c[i][j], Al_[i], Bf[jj][o],  Bf[jj][o + 1]);
            }
        if (more) { __syncthreads(); STS2(cur ^ 1); __syncthreads(); }
    }

    int gr = lane >> 2, gc = (lane & 3) * 2;
#pragma unroll
    for (int i = 0; i < 4; i++) {
#pragma unroll
        for (int half = 0; half < 2; half++) {
            int r = m0 + warpM + i * 16 + gr + half * 8;
            if (r < ne) {
                int   t = g_tok[e * T_TOK + r];
                float w = g_wt [e * T_TOK + r];
                float* op = out + (size_t)t * H_DIM + n0 + warpN;
#pragma unroll
                for (int j = 0; j < 4; j++) {
                    atomicAdd(op + j * 8 + gc,     w * c[i][j][2 * half]);
                    atomicAdd(op + j * 8 + gc + 1, w * c[i][j][2 * half + 1]);
                }
            }
        }
    }
#undef LDG2
#undef STS2
}

// ---------------------------------------------------------------------------
extern "C" void kernel_launch(void* const* d_in, const int* in_sizes, int n_in,
                              void* d_out, int out_size) {
    const float* x   = (const float*)d_in[0];
    const float* wr  = (const float*)d_in[1];
    const float* wi0 = (const float*)d_in[2];
    const float* wi1 = (const float*)d_in[3];
    const float* wo  = (const float*)d_in[4];
    float* out = (float*)d_out;

    int write_logits = (out_size >= T_TOK * H_DIM + T_TOK * E_NUM) ? 1 : 0;

    cudaMemsetAsync(out, 0, (size_t)T_TOK * H_DIM * sizeof(float));
    k_init<<<1, 32>>>();
    k_router<<<T_TOK / 8, 256>>>(x, wr, out + (size_t)T_TOK * H_DIM, write_logits);

    // pre-split fp32 -> fp16 hi/lo planes
    {
        __half *xh, *xl, *w0h, *w0l, *w1h, *w1l, *woh, *wol;
        cudaGetSymbolAddress((void**)&xh,  g_xh);  cudaGetSymbolAddress((void**)&xl,  g_xl);
        cudaGetSymbolAddress((void**)&w0h, g_w0h); cudaGetSymbolAddress((void**)&w0l, g_w0l);
        cudaGetSymbolAddress((void**)&w1h, g_w1h); cudaGetSymbolAddress((void**)&w1l, g_w1l);
        cudaGetSymbolAddress((void**)&woh, g_woh); cudaGetSymbolAddress((void**)&wol, g_wol);
        int nx = T_TOK * H_DIM / 4;
        int nw = E_NUM * H_DIM * I_DIM / 4;
        k_cvt<<<(nx + 255) / 256, 256>>>(x,   xh,  xl,  nx);
        k_cvt<<<(nw + 255) / 256, 256>>>(wi0, w0h, w0l, nw);
        k_cvt<<<(nw + 255) / 256, 256>>>(wi1, w1h, w1l, nw);
        k_cvt<<<(nw + 255) / 256, 256>>>(wo,  woh, wol, nw);
    }

    dim3 g1(T_TOK / 128, 12, E_NUM);
    k_mlp1<<<g1, 256>>>();

    int silu_blocks = (E_NUM * T_TOK * (I_DIM / 4)) / 256;
    k_silu<<<silu_blocks, 256>>>();

    dim3 g2(T_TOK / 128, H_DIM / 128, E_NUM);
    k_mlp2<<<g2, 256>>>(out);
}